// round 1
// baseline (speedup 1.0000x reference)
#include <cuda_runtime.h>
#include <cstdint>

// Problem shape (fixed by the dataset)
#define M_DIM 4096
#define K_DIM 4096
#define N_DIM 11008
#define KW (K_DIM / 4)   // packed int8x4 words per activation row = 1024
#define QW (K_DIM / 2)   // qweight int32 words per output row = 2048

// Scratch: packed int8 activations + per-row integer sums (no allocs allowed)
__device__ int g_qx[(size_t)M_DIM * KW];
__device__ int g_rowsum[M_DIM];

// mixed-sign dp4a: a = signed int8x4 (activations), b = unsigned int8x4 (nibbles 0..15)
__device__ __forceinline__ int dp4a_su(int a, int b, int c) {
    int d;
    asm("dp4a.s32.u32 %0, %1, %2, %3;" : "=r"(d) : "r"(a), "r"(b), "r"(c));
    return d;
}

// ---------------------------------------------------------------------------
// Kernel 1: static fake-quant of x -> packed int8, plus row sums.
// One block per row, 256 threads, each thread handles 4 float4 (16 values).
// ---------------------------------------------------------------------------
__global__ __launch_bounds__(256) void quantize_kernel(const float* __restrict__ x,
                                                       const float* __restrict__ clampv) {
    const int m = blockIdx.x;
    const float cv = clampv[0];
    const float a_scale = cv / 127.0f;   // matches reference fp32 division
    const float4* xrow = reinterpret_cast<const float4*>(x + (size_t)m * K_DIM);
    int* qrow = g_qx + (size_t)m * KW;

    int local_sum = 0;
#pragma unroll
    for (int t = 0; t < 4; t++) {
        const int w = threadIdx.x + 256 * t;      // packed-word index, coalesced
        float4 v = xrow[w];
        int q0 = __float2int_rn(fminf(fmaxf(v.x, -cv), cv) / a_scale);
        int q1 = __float2int_rn(fminf(fmaxf(v.y, -cv), cv) / a_scale);
        int q2 = __float2int_rn(fminf(fmaxf(v.z, -cv), cv) / a_scale);
        int q3 = __float2int_rn(fminf(fmaxf(v.w, -cv), cv) / a_scale);
        local_sum += q0 + q1 + q2 + q3;
        qrow[w] = (q0 & 0xFF) | ((q1 & 0xFF) << 8) | ((q2 & 0xFF) << 16) | ((q3 & 0xFF) << 24);
    }

    // block reduce local_sum -> g_rowsum[m]
    int s = local_sum;
#pragma unroll
    for (int off = 16; off > 0; off >>= 1) s += __shfl_down_sync(0xFFFFFFFFu, s, off);
    __shared__ int wsum[8];
    const int lane = threadIdx.x & 31, wid = threadIdx.x >> 5;
    if (lane == 0) wsum[wid] = s;
    __syncthreads();
    if (threadIdx.x == 0) {
        int tot = 0;
#pragma unroll
        for (int i = 0; i < 8; i++) tot += wsum[i];
        g_rowsum[m] = tot;
    }
}

// ---------------------------------------------------------------------------
// Kernel 2: s8 x u4 integer GEMM via dp4a.
// Block tile 128(M) x 128(N), K-chunk 64 (16 packed words). 256 threads,
// each thread computes an 8x8 register tile (rows ty+16i, cols tx+16j).
// ---------------------------------------------------------------------------
#define BK_WORDS 16            // packed words per K-chunk (= 64 k values)
#define SMEM_LD  132           // padded row length (words)

__global__ __launch_bounds__(256, 2) void gemm_kernel(const int* __restrict__ qweight,
                                                      const int* __restrict__ qzeros,
                                                      const float* __restrict__ scales,
                                                      const float* __restrict__ bias,
                                                      const float* __restrict__ clampv,
                                                      float* __restrict__ out) {
    __shared__ int a_s[BK_WORDS][SMEM_LD];   // [kk][m_local]
    __shared__ int b_s[BK_WORDS][SMEM_LD];   // [kk][n_local]

    const int tid = threadIdx.x;
    const int tx = tid & 15;         // column group
    const int ty = tid >> 4;         // row group
    const int n0 = blockIdx.x * 128;
    const int m0 = blockIdx.y * 128;

    int acc[8][8];
#pragma unroll
    for (int i = 0; i < 8; i++)
#pragma unroll
        for (int j = 0; j < 8; j++) acc[i][j] = 0;

    for (int kt = 0; kt < K_DIM / 64; kt++) {
        const int kw0 = kt * BK_WORDS;        // base packed-word index
        const int qj0 = kt * 32;              // base qweight-word index (2 k per word)

        // ---- load A tile: 128 rows x 16 packed words (512 int4 loads, 2/thread)
#pragma unroll
        for (int t = 0; t < 2; t++) {
            const int idx = tid + 256 * t;    // 0..511
            const int r = idx >> 2;           // row 0..127
            const int w4 = idx & 3;           // which int4 within the row
            int4 v = *reinterpret_cast<const int4*>(
                g_qx + (size_t)(m0 + r) * KW + kw0 + w4 * 4);
            a_s[w4 * 4 + 0][r] = v.x;
            a_s[w4 * 4 + 1][r] = v.y;
            a_s[w4 * 4 + 2][r] = v.z;
            a_s[w4 * 4 + 3][r] = v.w;
        }

        // ---- load + unpack B tile: 128 rows x 32 qweight words -> 16 packed words
#pragma unroll
        for (int t = 0; t < 4; t++) {
            const int idx = tid + 256 * t;    // 0..1023
            const int o = idx >> 3;           // out-row 0..127
            const int g = idx & 7;            // int4 group within the row
            int4 q = *reinterpret_cast<const int4*>(
                qweight + (size_t)(n0 + o) * QW + qj0 + g * 4);
            // word j covers k=2j (hi nibble) and k=2j+1 (lo nibble)
            int p0 = ((q.x >> 4) & 15) | ((q.x & 15) << 8) |
                     (((q.y >> 4) & 15) << 16) | ((q.y & 15) << 24);
            int p1 = ((q.z >> 4) & 15) | ((q.z & 15) << 8) |
                     (((q.w >> 4) & 15) << 16) | ((q.w & 15) << 24);
            b_s[2 * g + 0][o] = p0;
            b_s[2 * g + 1][o] = p1;
        }
        __syncthreads();

        // ---- compute
#pragma unroll
        for (int kk = 0; kk < BK_WORDS; kk++) {
            int a_frag[8], b_frag[8];
#pragma unroll
            for (int i = 0; i < 8; i++) a_frag[i] = a_s[kk][ty + 16 * i];
#pragma unroll
            for (int j = 0; j < 8; j++) b_frag[j] = b_s[kk][tx + 16 * j];
#pragma unroll
            for (int i = 0; i < 8; i++)
#pragma unroll
                for (int j = 0; j < 8; j++)
                    acc[i][j] = dp4a_su(a_frag[i], b_frag[j], acc[i][j]);
        }
        __syncthreads();
    }

    // ---- epilogue: out = a_scale*s_o*(acc - z_o*rowsum_m) + bias_o
    const float cv = clampv[0];
    const float a_scale = cv / 127.0f;

    float sc[8], bi[8];
    int zz[8];
#pragma unroll
    for (int j = 0; j < 8; j++) {
        const int o = n0 + tx + 16 * j;
        sc[j] = scales[o] * a_scale;
        zz[j] = qzeros[o];
        bi[j] = bias[o];
    }
#pragma unroll
    for (int i = 0; i < 8; i++) {
        const int m = m0 + ty + 16 * i;
        const int rs = g_rowsum[m];
        float* orow = out + (size_t)m * N_DIM + n0;
#pragma unroll
        for (int j = 0; j < 8; j++) {
            orow[tx + 16 * j] = sc[j] * (float)(acc[i][j] - zz[j] * rs) + bi[j];
        }
    }
}

// ---------------------------------------------------------------------------
extern "C" void kernel_launch(void* const* d_in, const int* in_sizes, int n_in,
                              void* d_out, int out_size) {
    const float* x       = (const float*)d_in[0];   // [4096, 4096] f32
    const int*   qweight = (const int*)  d_in[1];   // [11008, 2048] i32 (byte values)
    const int*   qzeros  = (const int*)  d_in[2];   // [11008, 1] i32
    const float* scales  = (const float*)d_in[3];   // [11008, 1] f32
    const float* bias    = (const float*)d_in[4];   // [11008] f32
    const float* clampv  = (const float*)d_in[5];   // [1] f32
    float* out = (float*)d_out;                     // [4096, 11008] f32

    quantize_kernel<<<M_DIM, 256>>>(x, clampv);
    gemm_kernel<<<dim3(N_DIM / 128, M_DIM / 128), 256>>>(qweight, qzeros, scales, bias,
                                                         clampv, out);
}

// round 3
// speedup vs baseline: 1.1099x; 1.1099x over previous
#include <cuda_runtime.h>
#include <cstdint>

// Problem shape (fixed by the dataset)
#define M_DIM 4096
#define K_DIM 4096
#define N_DIM 11008
#define KW 1024   // int32 words per row of packed s8 activations (K/4)
#define QW 2048   // qweight int32 words per output row (K/2)

// Scratch (no allocs allowed): packed s8 activations, unpacked s8 weights, row sums
__device__ int g_qx[(size_t)M_DIM * KW];      // 16 MB
__device__ int g_w [(size_t)N_DIM * KW];      // 45 MB
__device__ int g_rowsum[M_DIM];

// ---------------------------------------------------------------------------
// PTX helpers
// ---------------------------------------------------------------------------
__device__ __forceinline__ void cp16(uint32_t dst, const void* src) {
    asm volatile("cp.async.cg.shared.global [%0], [%1], 16;" :: "r"(dst), "l"(src));
}
__device__ __forceinline__ void cp_commit() {
    asm volatile("cp.async.commit_group;");
}
__device__ __forceinline__ void ldsm4(int& r0, int& r1, int& r2, int& r3, uint32_t addr) {
    asm volatile("ldmatrix.sync.aligned.m8n8.x4.shared.b16 {%0,%1,%2,%3}, [%4];"
                 : "=r"(r0), "=r"(r1), "=r"(r2), "=r"(r3) : "r"(addr));
}
__device__ __forceinline__ void mma_s8(int* d, const int* a, int b0, int b1) {
    asm volatile("mma.sync.aligned.m16n8k32.row.col.s32.s8.s8.s32 "
                 "{%0,%1,%2,%3}, {%4,%5,%6,%7}, {%8,%9}, {%0,%1,%2,%3};"
                 : "+r"(d[0]), "+r"(d[1]), "+r"(d[2]), "+r"(d[3])
                 : "r"(a[0]), "r"(a[1]), "r"(a[2]), "r"(a[3]), "r"(b0), "r"(b1));
}

// ---------------------------------------------------------------------------
// Kernel 1: static fake-quant of x -> packed s8 words + per-row sums.
// ---------------------------------------------------------------------------
__global__ __launch_bounds__(256) void quantize_kernel(const float* __restrict__ x,
                                                       const float* __restrict__ clampv) {
    const int m = blockIdx.x;
    const float cv = clampv[0];
    const float a_scale = cv / 127.0f;
    const float4* xrow = reinterpret_cast<const float4*>(x + (size_t)m * K_DIM);
    int* qrow = g_qx + (size_t)m * KW;

    int local_sum = 0;
#pragma unroll
    for (int t = 0; t < 4; t++) {
        const int w = threadIdx.x + 256 * t;
        float4 v = xrow[w];
        int q0 = __float2int_rn(fminf(fmaxf(v.x, -cv), cv) / a_scale);
        int q1 = __float2int_rn(fminf(fmaxf(v.y, -cv), cv) / a_scale);
        int q2 = __float2int_rn(fminf(fmaxf(v.z, -cv), cv) / a_scale);
        int q3 = __float2int_rn(fminf(fmaxf(v.w, -cv), cv) / a_scale);
        local_sum += q0 + q1 + q2 + q3;
        qrow[w] = (q0 & 0xFF) | ((q1 & 0xFF) << 8) | ((q2 & 0xFF) << 16) | ((q3 & 0xFF) << 24);
    }

    int s = local_sum;
#pragma unroll
    for (int off = 16; off > 0; off >>= 1) s += __shfl_down_sync(0xFFFFFFFFu, s, off);
    __shared__ int wsum[8];
    const int lane = threadIdx.x & 31, wid = threadIdx.x >> 5;
    if (lane == 0) wsum[wid] = s;
    __syncthreads();
    if (threadIdx.x == 0) {
        int tot = 0;
#pragma unroll
        for (int i = 0; i < 8; i++) tot += wsum[i];
        g_rowsum[m] = tot;
    }
}

// ---------------------------------------------------------------------------
// Kernel 2: unpack int4 nibbles -> s8 weight matrix g_w [N][K] (word-packed).
// ---------------------------------------------------------------------------
__global__ __launch_bounds__(256) void unpack_kernel(const int* __restrict__ qweight) {
    const int o = blockIdx.x;
    const int2* qrow = reinterpret_cast<const int2*>(qweight + (size_t)o * QW);
    int* wrow = g_w + (size_t)o * KW;
#pragma unroll
    for (int p = 0; p < 4; p++) {
        const int w = threadIdx.x + 256 * p;
        int2 q = qrow[w];
        wrow[w] = ((q.x >> 4) & 15) | ((q.x & 15) << 8) |
                  (((q.y >> 4) & 15) << 16) | ((q.y & 15) << 24);
    }
}

// ---------------------------------------------------------------------------
// Kernel 3: s8 x s8 IMMA GEMM. Block tile 128x128, BK=64 bytes, 8 warps (4Mx2N),
// warp tile 32x64 -> 2x8 mma(16x8x32) tiles. Double-buffered cp.async.
// Smem rows are 80 bytes: ldmatrix row-start bank quartet = 5*row mod 8, a
// permutation -> conflict-free without XOR swizzle.
//
// Fragment layouts (mma.m16n8k32.s8):
//   A regs: a0=r0-7/k0-15, a1=r8-15/k0-15, a2=r0-7/k16-31, a3=r8-15/k16-31
//     -> lrA toggles rows on lane bit3, lkA toggles k-half on lane bit4.
//   B regs: b0=k0-15, b1=k16-31 within an n-octet; next octet in regs 2,3
//     -> lrB toggles n-octet on lane bit4, lkB toggles k-half on lane bit3.
// ---------------------------------------------------------------------------
#define LDSS 80                   // smem row stride, bytes
#define STAGE_BYTES (128 * LDSS)  // 10240

__global__ __launch_bounds__(256, 2) void gemm_kernel(const int* __restrict__ qzeros,
                                                      const float* __restrict__ scales,
                                                      const float* __restrict__ bias,
                                                      const float* __restrict__ clampv,
                                                      float* __restrict__ out) {
    __shared__ __align__(16) char a_sm[2 * STAGE_BYTES];
    __shared__ __align__(16) char b_sm[2 * STAGE_BYTES];

    const int tid = threadIdx.x;
    const int wid = tid >> 5, lane = tid & 31;
    const int wm = wid & 3, wn = wid >> 2;           // 4 warps in M, 2 in N
    const int m0 = blockIdx.y * 128, n0 = blockIdx.x * 128;

    const uint32_t a_u32 = (uint32_t)__cvta_generic_to_shared(a_sm);
    const uint32_t b_u32 = (uint32_t)__cvta_generic_to_shared(b_sm);

    // A ldmatrix addressing: row-half on bit3, k-half on bit4
    const int lrA = (lane & 7) + ((lane >> 3) & 1) * 8;
    const int lkA = (lane >> 4) * 16;
    // B ldmatrix addressing: k-half on bit3, n-octet on bit4
    const int lrB = (lane & 7) + ((lane >> 4) << 3);
    const int lkB = ((lane >> 3) & 1) * 16;
    const uint32_t a_lm = a_u32 + (uint32_t)((wm * 32 + lrA) * LDSS + lkA);
    const uint32_t b_lm = b_u32 + (uint32_t)((wn * 64 + lrB) * LDSS + lkB);

    // cp.async tile-load indexing
    const int ldr = tid >> 2, ldc = tid & 3;

    int acc[2][8][4];
#pragma unroll
    for (int mt = 0; mt < 2; mt++)
#pragma unroll
        for (int nt = 0; nt < 8; nt++)
#pragma unroll
            for (int r = 0; r < 4; r++) acc[mt][nt][r] = 0;

    // ---- prologue: load stage 0 (kt=0)
    {
#pragma unroll
        for (int i = 0; i < 2; i++) {
            const int r = ldr + 64 * i;
            cp16(a_u32 + (uint32_t)(r * LDSS + ldc * 16), g_qx + (size_t)(m0 + r) * KW + ldc * 4);
            cp16(b_u32 + (uint32_t)(r * LDSS + ldc * 16), g_w  + (size_t)(n0 + r) * KW + ldc * 4);
        }
        cp_commit();
    }

#pragma unroll 1
    for (int kt = 0; kt < K_DIM / 64; kt++) {
        if (kt + 1 < K_DIM / 64) {
            const int stage = (kt + 1) & 1;
            const int kw0 = (kt + 1) * 16;
            const uint32_t ab = a_u32 + stage * STAGE_BYTES;
            const uint32_t bb = b_u32 + stage * STAGE_BYTES;
#pragma unroll
            for (int i = 0; i < 2; i++) {
                const int r = ldr + 64 * i;
                cp16(ab + (uint32_t)(r * LDSS + ldc * 16), g_qx + (size_t)(m0 + r) * KW + kw0 + ldc * 4);
                cp16(bb + (uint32_t)(r * LDSS + ldc * 16), g_w  + (size_t)(n0 + r) * KW + kw0 + ldc * 4);
            }
            cp_commit();
            asm volatile("cp.async.wait_group 1;");
        } else {
            asm volatile("cp.async.wait_group 0;");
        }
        __syncthreads();

        // ---- compute on stage kt&1
        const uint32_t ab = a_lm + (kt & 1) * STAGE_BYTES;
        const uint32_t bb = b_lm + (kt & 1) * STAGE_BYTES;
#pragma unroll
        for (int ks = 0; ks < 2; ks++) {
            int a[2][4], b[4][4];
            ldsm4(a[0][0], a[0][1], a[0][2], a[0][3], ab + ks * 32);
            ldsm4(a[1][0], a[1][1], a[1][2], a[1][3], ab + ks * 32 + 16 * LDSS);
#pragma unroll
            for (int p = 0; p < 4; p++)
                ldsm4(b[p][0], b[p][1], b[p][2], b[p][3], bb + ks * 32 + p * 16 * LDSS);
#pragma unroll
            for (int mt = 0; mt < 2; mt++)
#pragma unroll
                for (int nt = 0; nt < 8; nt++)
                    mma_s8(acc[mt][nt], a[mt], b[nt >> 1][(nt & 1) * 2], b[nt >> 1][(nt & 1) * 2 + 1]);
        }
        __syncthreads();
    }

    // ---- epilogue: out = a_scale*s_o*(acc - z_o*rowsum_m) + bias_o
    const float cv = clampv[0];
    const float a_scale = cv / 127.0f;
    const int g = lane >> 2, tg = lane & 3;

    float scf[8][2], bif[8][2];
    int zzf[8][2];
#pragma unroll
    for (int nt = 0; nt < 8; nt++) {
        const int col = n0 + wn * 64 + nt * 8 + tg * 2;
#pragma unroll
        for (int j = 0; j < 2; j++) {
            scf[nt][j] = scales[col + j] * a_scale;
            zzf[nt][j] = qzeros[col + j];
            bif[nt][j] = bias[col + j];
        }
    }

#pragma unroll
    for (int mt = 0; mt < 2; mt++)
#pragma unroll
        for (int h = 0; h < 2; h++) {
            const int row = m0 + wm * 32 + mt * 16 + h * 8 + g;
            const int rs = g_rowsum[row];
            float* orow = out + (size_t)row * N_DIM + n0 + wn * 64;
#pragma unroll
            for (int nt = 0; nt < 8; nt++) {
                float2 v;
                v.x = scf[nt][0] * (float)(acc[mt][nt][h * 2 + 0] - zzf[nt][0] * rs) + bif[nt][0];
                v.y = scf[nt][1] * (float)(acc[mt][nt][h * 2 + 1] - zzf[nt][1] * rs) + bif[nt][1];
                *reinterpret_cast<float2*>(orow + nt * 8 + tg * 2) = v;
            }
        }
}

// ---------------------------------------------------------------------------
extern "C" void kernel_launch(void* const* d_in, const int* in_sizes, int n_in,
                              void* d_out, int out_size) {
    const float* x       = (const float*)d_in[0];   // [4096, 4096] f32
    const int*   qweight = (const int*)  d_in[1];   // [11008, 2048] i32
    const int*   qzeros  = (const int*)  d_in[2];   // [11008, 1] i32
    const float* scales  = (const float*)d_in[3];   // [11008, 1] f32
    const float* bias    = (const float*)d_in[4];   // [11008] f32
    const float* clampv  = (const float*)d_in[5];   // [1] f32
    float* out = (float*)d_out;                     // [4096, 11008] f32

    quantize_kernel<<<M_DIM, 256>>>(x, clampv);
    unpack_kernel<<<N_DIM, 256>>>(qweight);
    gemm_kernel<<<dim3(N_DIM / 128, M_DIM / 128), 256>>>(qzeros, scales, bias, clampv, out);
}

// round 5
// speedup vs baseline: 2.6432x; 2.3815x over previous
#include <cuda_runtime.h>
#include <cstdint>

// Problem shape (fixed by the dataset)
#define M_DIM 4096
#define K_DIM 4096
#define N_DIM 11008
#define KW 1024   // int32 words per row of packed activations (K/4)
#define QW 2048   // qweight int32 words per output row (K/2)

// Scratch (no allocs allowed). Both matrices stored with the K-permutation:
// within each 16-byte group, stored word c holds logical k {2c,2c+1,8+2c,9+2c}.
// g_qx bytes are biased: stored = q + 128 (q in [-127,127]).
// g_w  bytes are plain nibble values 0..15.
__device__ int g_qx[(size_t)M_DIM * KW];      // 16 MB
__device__ int g_w [(size_t)N_DIM * KW];      // 45 MB
__device__ int g_rowsum[M_DIM];

#define A_BIAS 0x64806480u   // f16x2 (1152,1152): 1024 + 128 byte-bias
#define B_BIAS 0x64006400u   // f16x2 (1024,1024)

// ---------------------------------------------------------------------------
// PTX helpers
// ---------------------------------------------------------------------------
__device__ __forceinline__ void cp16(uint32_t dst, const void* src) {
    asm volatile("cp.async.cg.shared.global [%0], [%1], 16;" :: "r"(dst), "l"(src));
}
#define CP_COMMIT() asm volatile("cp.async.commit_group;")
__device__ __forceinline__ void ldsm4(int& r0, int& r1, int& r2, int& r3, uint32_t addr) {
    asm volatile("ldmatrix.sync.aligned.m8n8.x4.shared.b16 {%0,%1,%2,%3}, [%4];"
                 : "=r"(r0), "=r"(r1), "=r"(r2), "=r"(r3) : "r"(addr));
}
// Byte pair -> f16x2: r = [b, 0x64, b', 0x64] via prmt, then subtract bias.
__device__ __forceinline__ uint32_t cvt_pair(int v, uint32_t sel, uint32_t bias) {
    uint32_t r;
    asm("prmt.b32 %0, %1, %2, %3;" : "=r"(r) : "r"(v), "r"(0x64646464u), "r"(sel));
    asm("sub.rn.f16x2 %0, %0, %1;" : "+r"(r) : "r"(bias));
    return r;
}
__device__ __forceinline__ void mma_f16(float* d, const uint32_t* a, uint32_t b0, uint32_t b1) {
    asm volatile("mma.sync.aligned.m16n8k16.row.col.f32.f16.f16.f32 "
                 "{%0,%1,%2,%3}, {%4,%5,%6,%7}, {%8,%9}, {%0,%1,%2,%3};"
                 : "+f"(d[0]), "+f"(d[1]), "+f"(d[2]), "+f"(d[3])
                 : "r"(a[0]), "r"(a[1]), "r"(a[2]), "r"(a[3]), "r"(b0), "r"(b1));
}

// ---------------------------------------------------------------------------
// Kernel 1: static fake-quant of x -> permuted, biased s8 bytes + row sums.
// Thread t handles logical k [16t, 16t+16) of its row.
// ---------------------------------------------------------------------------
__global__ __launch_bounds__(256) void quantize_kernel(const float* __restrict__ x,
                                                       const float* __restrict__ clampv) {
    const int m = blockIdx.x;
    const float cv = clampv[0];
    const float a_scale = cv / 127.0f;
    const float* xrow = x + (size_t)m * K_DIM;
    const int t = threadIdx.x;

    int q[16];
    int local_sum = 0;
#pragma unroll
    for (int i = 0; i < 4; i++) {
        float4 v = *reinterpret_cast<const float4*>(xrow + 16 * t + 4 * i);
        q[4 * i + 0] = __float2int_rn(fminf(fmaxf(v.x, -cv), cv) / a_scale);
        q[4 * i + 1] = __float2int_rn(fminf(fmaxf(v.y, -cv), cv) / a_scale);
        q[4 * i + 2] = __float2int_rn(fminf(fmaxf(v.z, -cv), cv) / a_scale);
        q[4 * i + 3] = __float2int_rn(fminf(fmaxf(v.w, -cv), cv) / a_scale);
    }
#pragma unroll
    for (int i = 0; i < 16; i++) local_sum += q[i];

    int4 w;
    int* wp = &w.x;
#pragma unroll
    for (int c = 0; c < 4; c++) {
        wp[c] = ((q[2 * c]     + 128) & 0xFF)
              | ((q[2 * c + 1] + 128) & 0xFF) << 8
              | ((q[8 + 2 * c] + 128) & 0xFF) << 16
              | ((q[9 + 2 * c] + 128) & 0xFF) << 24;
    }
    *reinterpret_cast<int4*>(g_qx + (size_t)m * KW + 4 * t) = w;

    int s = local_sum;
#pragma unroll
    for (int off = 16; off > 0; off >>= 1) s += __shfl_down_sync(0xFFFFFFFFu, s, off);
    __shared__ int wsum[8];
    const int lane = threadIdx.x & 31, wid = threadIdx.x >> 5;
    if (lane == 0) wsum[wid] = s;
    __syncthreads();
    if (threadIdx.x == 0) {
        int tot = 0;
#pragma unroll
        for (int i = 0; i < 8; i++) tot += wsum[i];
        g_rowsum[m] = tot;
    }
}

// ---------------------------------------------------------------------------
// Kernel 2: unpack int4 nibbles -> permuted s8 weights.
// Thread t handles logical k [16t,16t+16): qwords 8t..8t+7.
// logical k=2j from hi nibble of qword j, k=2j+1 from lo nibble.
// out word c = [hi(q[c]), lo(q[c]), hi(q[c+4]), lo(q[c+4])]
// ---------------------------------------------------------------------------
__global__ __launch_bounds__(256) void unpack_kernel(const int* __restrict__ qweight) {
    const int o = blockIdx.x;
    const int t = threadIdx.x;
    const int* qrow = qweight + (size_t)o * QW + 8 * t;
    int4 q0 = *reinterpret_cast<const int4*>(qrow);
    int4 q1 = *reinterpret_cast<const int4*>(qrow + 4);
    const int* ql = &q0.x;
    const int* qh = &q1.x;
    int4 w;
    int* wp = &w.x;
#pragma unroll
    for (int c = 0; c < 4; c++) {
        wp[c] = ((ql[c] >> 4) & 15) | ((ql[c] & 15) << 8) |
                (((qh[c] >> 4) & 15) << 16) | ((qh[c] & 15) << 24);
    }
    *reinterpret_cast<int4*>(g_w + (size_t)o * KW + 4 * t) = w;
}

// ---------------------------------------------------------------------------
// Kernel 3: HMMA GEMM on s8-in-smem operands with register f16 conversion.
// Block tile 128x128, BK=64 bytes, 8 warps (4Mx2N), warp tile 32x64.
// Double-buffered cp.async; smem rows 80 bytes (conflict-free, proven R3).
// ---------------------------------------------------------------------------
#define LDSS 80
#define STAGE_BYTES (128 * LDSS)

__global__ __launch_bounds__(256, 1) void gemm_kernel(const int* __restrict__ qzeros,
                                                      const float* __restrict__ scales,
                                                      const float* __restrict__ bias,
                                                      const float* __restrict__ clampv,
                                                      float* __restrict__ out) {
    __shared__ __align__(16) char a_sm[2 * STAGE_BYTES];
    __shared__ __align__(16) char b_sm[2 * STAGE_BYTES];

    const int tid = threadIdx.x;
    const int wid = tid >> 5, lane = tid & 31;
    const int wm = wid & 3, wn = wid >> 2;           // 4 warps in M, 2 in N
    const int m0 = blockIdx.y * 128, n0 = blockIdx.x * 128;

    const uint32_t a_u32 = (uint32_t)__cvta_generic_to_shared(a_sm);
    const uint32_t b_u32 = (uint32_t)__cvta_generic_to_shared(b_sm);

    // A ldmatrix addressing: row-half on bit3, k-half on bit4 (proven R3)
    const int lrA = (lane & 7) + ((lane >> 3) & 1) * 8;
    const int lkA = (lane >> 4) * 16;
    // B ldmatrix addressing: k-half on bit3, n-octet on bit4 (proven R3)
    const int lrB = (lane & 7) + ((lane >> 4) << 3);
    const int lkB = ((lane >> 3) & 1) * 16;
    const uint32_t a_lm = a_u32 + (uint32_t)((wm * 32 + lrA) * LDSS + lkA);
    const uint32_t b_lm = b_u32 + (uint32_t)((wn * 64 + lrB) * LDSS + lkB);

    const int ldr = tid >> 2, ldc = tid & 3;

    float acc[2][8][4];
#pragma unroll
    for (int mt = 0; mt < 2; mt++)
#pragma unroll
        for (int nt = 0; nt < 8; nt++)
#pragma unroll
            for (int r = 0; r < 4; r++) acc[mt][nt][r] = 0.0f;

    // ---- prologue: load stage 0
    {
#pragma unroll
        for (int i = 0; i < 2; i++) {
            const int r = ldr + 64 * i;
            cp16(a_u32 + (uint32_t)(r * LDSS + ldc * 16), g_qx + (size_t)(m0 + r) * KW + ldc * 4);
            cp16(b_u32 + (uint32_t)(r * LDSS + ldc * 16), g_w  + (size_t)(n0 + r) * KW + ldc * 4);
        }
        CP_COMMIT();
    }

#pragma unroll 1
    for (int kt = 0; kt < K_DIM / 64; kt++) {
        if (kt + 1 < K_DIM / 64) {
            const int stage = (kt + 1) & 1;
            const int kw0 = (kt + 1) * 16;
            const uint32_t ab = a_u32 + stage * STAGE_BYTES;
            const uint32_t bb = b_u32 + stage * STAGE_BYTES;
#pragma unroll
            for (int i = 0; i < 2; i++) {
                const int r = ldr + 64 * i;
                cp16(ab + (uint32_t)(r * LDSS + ldc * 16), g_qx + (size_t)(m0 + r) * KW + kw0 + ldc * 4);
                cp16(bb + (uint32_t)(r * LDSS + ldc * 16), g_w  + (size_t)(n0 + r) * KW + kw0 + ldc * 4);
            }
            CP_COMMIT();
            asm volatile("cp.async.wait_group 1;");
        } else {
            asm volatile("cp.async.wait_group 0;");
        }
        __syncthreads();

        const uint32_t ab = a_lm + (kt & 1) * STAGE_BYTES;
        const uint32_t bb = b_lm + (kt & 1) * STAGE_BYTES;
#pragma unroll
        for (int ks = 0; ks < 2; ks++) {
            int a8[2][4], b8[4][4];
            ldsm4(a8[0][0], a8[0][1], a8[0][2], a8[0][3], ab + ks * 32);
            ldsm4(a8[1][0], a8[1][1], a8[1][2], a8[1][3], ab + ks * 32 + 16 * LDSS);
#pragma unroll
            for (int p = 0; p < 4; p++)
                ldsm4(b8[p][0], b8[p][1], b8[p][2], b8[p][3], bb + ks * 32 + p * 16 * LDSS);

            // s8 reg (permuted layout): low byte-pair = f16 frag reg for k(2c,2c+1),
            // high pair = k(8+2c,9+2c). Two f16 k16-steps per 32-byte group.
#pragma unroll
            for (int h = 0; h < 2; h++) {
                uint32_t bf[8][2];
#pragma unroll
                for (int o = 0; o < 8; o++) {
                    const int src = b8[o >> 1][(o & 1) * 2 + h];
                    bf[o][0] = cvt_pair(src, 0x4140u, B_BIAS);
                    bf[o][1] = cvt_pair(src, 0x4342u, B_BIAS);
                }
#pragma unroll
                for (int mt = 0; mt < 2; mt++) {
                    uint32_t af[4];
                    af[0] = cvt_pair(a8[mt][2 * h + 0], 0x4140u, A_BIAS);
                    af[1] = cvt_pair(a8[mt][2 * h + 1], 0x4140u, A_BIAS);
                    af[2] = cvt_pair(a8[mt][2 * h + 0], 0x4342u, A_BIAS);
                    af[3] = cvt_pair(a8[mt][2 * h + 1], 0x4342u, A_BIAS);
#pragma unroll
                    for (int o = 0; o < 8; o++)
                        mma_f16(acc[mt][o], af, bf[o][0], bf[o][1]);
                }
            }
        }
        __syncthreads();
    }

    // ---- epilogue: out = sc*(acc - z*rowsum) + bias (all values exact integers)
    const float cv = clampv[0];
    const float a_scale = cv / 127.0f;
    const int g = lane >> 2, tg = lane & 3;

    float scf[8][2], bif[8][2], zzf[8][2];
#pragma unroll
    for (int nt = 0; nt < 8; nt++) {
        const int col = n0 + wn * 64 + nt * 8 + tg * 2;
#pragma unroll
        for (int j = 0; j < 2; j++) {
            scf[nt][j] = scales[col + j] * a_scale;
            zzf[nt][j] = (float)qzeros[col + j];
            bif[nt][j] = bias[col + j];
        }
    }

#pragma unroll
    for (int mt = 0; mt < 2; mt++)
#pragma unroll
        for (int h = 0; h < 2; h++) {
            const int row = m0 + wm * 32 + mt * 16 + h * 8 + g;
            const float rs = (float)g_rowsum[row];
            float* orow = out + (size_t)row * N_DIM + n0 + wn * 64;
#pragma unroll
            for (int nt = 0; nt < 8; nt++) {
                float2 v;
                v.x = scf[nt][0] * (acc[mt][nt][h * 2 + 0] - zzf[nt][0] * rs) + bif[nt][0];
                v.y = scf[nt][1] * (acc[mt][nt][h * 2 + 1] - zzf[nt][1] * rs) + bif[nt][1];
                *reinterpret_cast<float2*>(orow + nt * 8 + tg * 2) = v;
            }
        }
}

// ---------------------------------------------------------------------------
extern "C" void kernel_launch(void* const* d_in, const int* in_sizes, int n_in,
                              void* d_out, int out_size) {
    const float* x       = (const float*)d_in[0];   // [4096, 4096] f32
    const int*   qweight = (const int*)  d_in[1];   // [11008, 2048] i32
    const int*   qzeros  = (const int*)  d_in[2];   // [11008, 1] i32
    const float* scales  = (const float*)d_in[3];   // [11008, 1] f32
    const float* bias    = (const float*)d_in[4];   // [11008] f32
    const float* clampv  = (const float*)d_in[5];   // [1] f32
    float* out = (float*)d_out;                     // [4096, 11008] f32

    quantize_kernel<<<M_DIM, 256>>>(x, clampv);
    unpack_kernel<<<N_DIM, 256>>>(qweight);
    gemm_kernel<<<dim3(N_DIM / 128, M_DIM / 128), 256>>>(qzeros, scales, bias, clampv, out);
}

// round 8
// speedup vs baseline: 2.9017x; 1.0978x over previous
#include <cuda_runtime.h>
#include <cuda_fp16.h>
#include <cstdint>

// Problem shape (fixed by the dataset)
#define M_DIM 4096
#define K_DIM 4096
#define N_DIM 11008
#define QW 2048   // qweight int32 words per output row (one byte value per word... K/2)

// Scratch (no allocs allowed): f16 operands + row sums
__device__ __half g_xh[(size_t)M_DIM * K_DIM];   // 32 MB, exact integer q in [-127,127]
__device__ __half g_wh[(size_t)N_DIM * K_DIM];   // 90 MB, exact integer w in [0,15]
__device__ int g_rowsum[M_DIM];

// ---------------------------------------------------------------------------
// PTX helpers
// ---------------------------------------------------------------------------
__device__ __forceinline__ void cp16(uint32_t dst, const void* src) {
    asm volatile("cp.async.cg.shared.global [%0], [%1], 16;" :: "r"(dst), "l"(src));
}
#define CP_COMMIT() asm volatile("cp.async.commit_group;")
__device__ __forceinline__ void ldsm4(int& r0, int& r1, int& r2, int& r3, uint32_t addr) {
    asm volatile("ldmatrix.sync.aligned.m8n8.x4.shared.b16 {%0,%1,%2,%3}, [%4];"
                 : "=r"(r0), "=r"(r1), "=r"(r2), "=r"(r3) : "r"(addr));
}
__device__ __forceinline__ void mma_f16(float* d, const int* a, int b0, int b1) {
    asm volatile("mma.sync.aligned.m16n8k16.row.col.f32.f16.f16.f32 "
                 "{%0,%1,%2,%3}, {%4,%5,%6,%7}, {%8,%9}, {%0,%1,%2,%3};"
                 : "+f"(d[0]), "+f"(d[1]), "+f"(d[2]), "+f"(d[3])
                 : "r"(a[0]), "r"(a[1]), "r"(a[2]), "r"(a[3]), "r"(b0), "r"(b1));
}

// ---------------------------------------------------------------------------
// Kernel 1: static fake-quant of x -> exact f16 integers + per-row sums.
// Thread t handles k [16t, 16t+16) of row blockIdx.x.
// ---------------------------------------------------------------------------
__global__ __launch_bounds__(256) void quantize_kernel(const float* __restrict__ x,
                                                       const float* __restrict__ clampv) {
    const int m = blockIdx.x;
    const float cv = clampv[0];
    const float a_scale = cv / 127.0f;
    const float* xrow = x + (size_t)m * K_DIM;
    const int t = threadIdx.x;

    int q[16];
#pragma unroll
    for (int i = 0; i < 4; i++) {
        float4 v = *reinterpret_cast<const float4*>(xrow + 16 * t + 4 * i);
        q[4 * i + 0] = __float2int_rn(fminf(fmaxf(v.x, -cv), cv) / a_scale);
        q[4 * i + 1] = __float2int_rn(fminf(fmaxf(v.y, -cv), cv) / a_scale);
        q[4 * i + 2] = __float2int_rn(fminf(fmaxf(v.z, -cv), cv) / a_scale);
        q[4 * i + 3] = __float2int_rn(fminf(fmaxf(v.w, -cv), cv) / a_scale);
    }
    int local_sum = 0;
#pragma unroll
    for (int i = 0; i < 16; i++) local_sum += q[i];

    __half2 h[8];
#pragma unroll
    for (int i = 0; i < 8; i++)
        h[i] = __halves2half2(__int2half_rn(q[2 * i]), __int2half_rn(q[2 * i + 1]));
    __half* dst = g_xh + (size_t)m * K_DIM + 16 * t;
    *reinterpret_cast<int4*>(dst)     = *reinterpret_cast<int4*>(&h[0]);
    *reinterpret_cast<int4*>(dst + 8) = *reinterpret_cast<int4*>(&h[4]);

    int s = local_sum;
#pragma unroll
    for (int off = 16; off > 0; off >>= 1) s += __shfl_down_sync(0xFFFFFFFFu, s, off);
    __shared__ int wsum[8];
    const int lane = threadIdx.x & 31, wid = threadIdx.x >> 5;
    if (lane == 0) wsum[wid] = s;
    __syncthreads();
    if (threadIdx.x == 0) {
        int tot = 0;
#pragma unroll
        for (int i = 0; i < 8; i++) tot += wsum[i];
        g_rowsum[m] = tot;
    }
}

// ---------------------------------------------------------------------------
// Kernel 2: unpack int4 nibbles -> exact f16 weights.
// qword j holds one byte: k=2j from hi nibble, k=2j+1 from lo nibble.
// Thread t handles qwords 8t..8t+7 -> k [16t, 16t+16).
// ---------------------------------------------------------------------------
__global__ __launch_bounds__(256) void unpack_kernel(const int* __restrict__ qweight) {
    const int o = blockIdx.x;
    const int t = threadIdx.x;
    const int* qrow = qweight + (size_t)o * QW + 8 * t;
    int4 q0 = *reinterpret_cast<const int4*>(qrow);
    int4 q1 = *reinterpret_cast<const int4*>(qrow + 4);
    const int* ql = &q0.x;
    const int* qh = &q1.x;

    __half2 h[8];
#pragma unroll
    for (int c = 0; c < 4; c++) {
        h[c]     = __halves2half2(__int2half_rn((ql[c] >> 4) & 15), __int2half_rn(ql[c] & 15));
        h[4 + c] = __halves2half2(__int2half_rn((qh[c] >> 4) & 15), __int2half_rn(qh[c] & 15));
    }
    __half* dst = g_wh + (size_t)o * K_DIM + 16 * t;
    *reinterpret_cast<int4*>(dst)     = *reinterpret_cast<int4*>(&h[0]);
    *reinterpret_cast<int4*>(dst + 8) = *reinterpret_cast<int4*>(&h[4]);
}

// ---------------------------------------------------------------------------
// Kernel 3: pure-HMMA f16 GEMM, exact integer math.
// Block tile 128x128, BK=64 k-values (128B rows), 8 warps (4Mx2N),
// warp tile 32x64. Double-buffered cp.async, XOR-swizzled 128B smem rows.
// ldmatrix f16 canonical mapping: lane row = lane&15, 16B segment = lane>>4.
// ---------------------------------------------------------------------------
#define BK 64
#define ROWB 128                    // bytes per smem row (= BK*2)
#define A_STG (128 * ROWB)          // 16 KB
#define STG (2 * A_STG)             // 32 KB per stage (A + B)
#define NCHUNK (K_DIM / BK)         // 64

__global__ __launch_bounds__(256) void gemm_kernel(const int* __restrict__ qzeros,
                                                   const float* __restrict__ scales,
                                                   const float* __restrict__ bias,
                                                   const float* __restrict__ clampv,
                                                   float* __restrict__ out) {
    extern __shared__ __align__(128) char smem[];
    const uint32_t sb = (uint32_t)__cvta_generic_to_shared(smem);

    const int tid = threadIdx.x;
    const int wid = tid >> 5, lane = tid & 31;
    const int wm = wid & 3, wn = wid >> 2;           // 4 warps in M, 2 in N
    const int m0 = blockIdx.y * 128, n0 = blockIdx.x * 128;

    // ldmatrix per-lane addressing
    const int rin = lane & 15, seg = lane >> 4;
    int arow[2], akey[2];
#pragma unroll
    for (int mt = 0; mt < 2; mt++) {
        const int r = wm * 32 + mt * 16 + rin;
        arow[mt] = r * ROWB;
        akey[mt] = r & 7;
    }
    int brow[4], bkey[4];
#pragma unroll
    for (int oc = 0; oc < 4; oc++) {
        const int r = wn * 64 + oc * 16 + rin;
        brow[oc] = r * ROWB;
        bkey[oc] = r & 7;
    }

    // cp.async per-thread mapping: 128 rows x 8 chunks of 16B per matrix
    const int ldc = tid & 7;     // 16B chunk
    const int ldr = tid >> 3;    // row 0..31 (+32*i)

    float acc[2][8][4];
#pragma unroll
    for (int mt = 0; mt < 2; mt++)
#pragma unroll
        for (int o = 0; o < 8; o++)
#pragma unroll
            for (int r = 0; r < 4; r++) acc[mt][o][r] = 0.0f;

    auto load_chunk = [&](int kt, int stage) {
        const uint32_t ab = sb + stage * STG;
        const uint32_t bb = ab + A_STG;
        const size_t koff = (size_t)kt * BK + ldc * 8;   // halves
#pragma unroll
        for (int i = 0; i < 4; i++) {
            const int r = ldr + 32 * i;
            const uint32_t sw = (uint32_t)(r * ROWB + ((ldc ^ (r & 7)) << 4));
            cp16(ab + sw, g_xh + (size_t)(m0 + r) * K_DIM + koff);
            cp16(bb + sw, g_wh + (size_t)(n0 + r) * K_DIM + koff);
        }
        CP_COMMIT();
    };

    load_chunk(0, 0);

#pragma unroll 1
    for (int kt = 0; kt < NCHUNK; kt++) {
        if (kt + 1 < NCHUNK) {
            load_chunk(kt + 1, (kt + 1) & 1);
            asm volatile("cp.async.wait_group 1;");
        } else {
            asm volatile("cp.async.wait_group 0;");
        }
        __syncthreads();

        const uint32_t ab = sb + (kt & 1) * STG;
        const uint32_t bb = ab + A_STG;
#pragma unroll
        for (int s = 0; s < 4; s++) {               // four k16 steps
            const int cidx = 2 * s + seg;
            int a[2][4], b[4][4];
#pragma unroll
            for (int mt = 0; mt < 2; mt++)
                ldsm4(a[mt][0], a[mt][1], a[mt][2], a[mt][3],
                      ab + (uint32_t)(arow[mt] + ((cidx ^ akey[mt]) << 4)));
#pragma unroll
            for (int oc = 0; oc < 4; oc++)
                ldsm4(b[oc][0], b[oc][1], b[oc][2], b[oc][3],
                      bb + (uint32_t)(brow[oc] + ((cidx ^ bkey[oc]) << 4)));
#pragma unroll
            for (int mt = 0; mt < 2; mt++)
#pragma unroll
                for (int oc = 0; oc < 4; oc++) {
                    mma_f16(acc[mt][oc * 2 + 0], a[mt], b[oc][0], b[oc][2]);
                    mma_f16(acc[mt][oc * 2 + 1], a[mt], b[oc][1], b[oc][3]);
                }
        }
        __syncthreads();
    }

    // ---- epilogue: out = sc*(acc - z*rowsum) + bias (all exact integers)
    const float cv = clampv[0];
    const float a_scale = cv / 127.0f;
    const int g = lane >> 2, tg = lane & 3;

    float scf[8][2], bif[8][2], zzf[8][2];
#pragma unroll
    for (int o = 0; o < 8; o++) {
        const int col = n0 + wn * 64 + (o >> 1) * 16 + (o & 1) * 8 + tg * 2;
#pragma unroll
        for (int j = 0; j < 2; j++) {
            scf[o][j] = scales[col + j] * a_scale;
            zzf[o][j] = (float)qzeros[col + j];
            bif[o][j] = bias[col + j];
        }
    }

#pragma unroll
    for (int mt = 0; mt < 2; mt++)
#pragma unroll
        for (int h = 0; h < 2; h++) {
            const int row = m0 + wm * 32 + mt * 16 + h * 8 + g;
            const float rs = (float)g_rowsum[row];
            float* orow = out + (size_t)row * N_DIM + n0 + wn * 64;
#pragma unroll
            for (int o = 0; o < 8; o++) {
                float2 v;
                v.x = scf[o][0] * (acc[mt][o][h * 2 + 0] - zzf[o][0] * rs) + bif[o][0];
                v.y = scf[o][1] * (acc[mt][o][h * 2 + 1] - zzf[o][1] * rs) + bif[o][1];
                *reinterpret_cast<float2*>(orow + (o >> 1) * 16 + (o & 1) * 8 + tg * 2) = v;
            }
        }
}

// ---------------------------------------------------------------------------
extern "C" void kernel_launch(void* const* d_in, const int* in_sizes, int n_in,
                              void* d_out, int out_size) {
    const float* x       = (const float*)d_in[0];   // [4096, 4096] f32
    const int*   qweight = (const int*)  d_in[1];   // [11008, 2048] i32
    const int*   qzeros  = (const int*)  d_in[2];   // [11008, 1] i32
    const float* scales  = (const float*)d_in[3];   // [11008, 1] f32
    const float* bias    = (const float*)d_in[4];   // [11008] f32
    const float* clampv  = (const float*)d_in[5];   // [1] f32
    float* out = (float*)d_out;                     // [4096, 11008] f32

    cudaFuncSetAttribute(gemm_kernel, cudaFuncAttributeMaxDynamicSharedMemorySize, 2 * STG);

    quantize_kernel<<<M_DIM, 256>>>(x, clampv);
    unpack_kernel<<<N_DIM, 256>>>(qweight);
    gemm_kernel<<<dim3(N_DIM / 128, M_DIM / 128), 256, 2 * STG>>>(qzeros, scales, bias,
                                                                  clampv, out);
}

// round 9
// speedup vs baseline: 2.9578x; 1.0193x over previous
#include <cuda_runtime.h>
#include <cuda_fp16.h>
#include <cstdint>

// Problem shape (fixed by the dataset)
#define M_DIM 4096
#define K_DIM 4096
#define N_DIM 11008
#define QW 2048   // qweight int32 words per output row (K/2)

// Scratch (no allocs allowed): f16 operands + row sums
__device__ __half g_xh[(size_t)M_DIM * K_DIM];   // 32 MB, exact integer q in [-127,127]
__device__ __half g_wh[(size_t)N_DIM * K_DIM];   // 90 MB, exact integer w in [0,15]
__device__ int g_rowsum[M_DIM];

// ---------------------------------------------------------------------------
// PTX helpers
// ---------------------------------------------------------------------------
__device__ __forceinline__ void cp16(uint32_t dst, const void* src) {
    asm volatile("cp.async.cg.shared.global [%0], [%1], 16;" :: "r"(dst), "l"(src));
}
#define CP_COMMIT() asm volatile("cp.async.commit_group;")
__device__ __forceinline__ void ldsm4(int& r0, int& r1, int& r2, int& r3, uint32_t addr) {
    asm volatile("ldmatrix.sync.aligned.m8n8.x4.shared.b16 {%0,%1,%2,%3}, [%4];"
                 : "=r"(r0), "=r"(r1), "=r"(r2), "=r"(r3) : "r"(addr));
}
__device__ __forceinline__ void mma_f16(float* d, const int* a, int b0, int b1) {
    asm volatile("mma.sync.aligned.m16n8k16.row.col.f32.f16.f16.f32 "
                 "{%0,%1,%2,%3}, {%4,%5,%6,%7}, {%8,%9}, {%0,%1,%2,%3};"
                 : "+f"(d[0]), "+f"(d[1]), "+f"(d[2]), "+f"(d[3])
                 : "r"(a[0]), "r"(a[1]), "r"(a[2]), "r"(a[3]), "r"(b0), "r"(b1));
}

// ---------------------------------------------------------------------------
// Kernel 1: static fake-quant of x -> exact f16 integers + per-row sums.
// ---------------------------------------------------------------------------
__global__ __launch_bounds__(256) void quantize_kernel(const float* __restrict__ x,
                                                       const float* __restrict__ clampv) {
    const int m = blockIdx.x;
    const float cv = clampv[0];
    const float a_scale = cv / 127.0f;
    const float* xrow = x + (size_t)m * K_DIM;
    const int t = threadIdx.x;

    int q[16];
#pragma unroll
    for (int i = 0; i < 4; i++) {
        float4 v = *reinterpret_cast<const float4*>(xrow + 16 * t + 4 * i);
        q[4 * i + 0] = __float2int_rn(fminf(fmaxf(v.x, -cv), cv) / a_scale);
        q[4 * i + 1] = __float2int_rn(fminf(fmaxf(v.y, -cv), cv) / a_scale);
        q[4 * i + 2] = __float2int_rn(fminf(fmaxf(v.z, -cv), cv) / a_scale);
        q[4 * i + 3] = __float2int_rn(fminf(fmaxf(v.w, -cv), cv) / a_scale);
    }
    int local_sum = 0;
#pragma unroll
    for (int i = 0; i < 16; i++) local_sum += q[i];

    __half2 h[8];
#pragma unroll
    for (int i = 0; i < 8; i++)
        h[i] = __halves2half2(__int2half_rn(q[2 * i]), __int2half_rn(q[2 * i + 1]));
    __half* dst = g_xh + (size_t)m * K_DIM + 16 * t;
    *reinterpret_cast<int4*>(dst)     = *reinterpret_cast<int4*>(&h[0]);
    *reinterpret_cast<int4*>(dst + 8) = *reinterpret_cast<int4*>(&h[4]);

    int s = local_sum;
#pragma unroll
    for (int off = 16; off > 0; off >>= 1) s += __shfl_down_sync(0xFFFFFFFFu, s, off);
    __shared__ int wsum[8];
    const int lane = threadIdx.x & 31, wid = threadIdx.x >> 5;
    if (lane == 0) wsum[wid] = s;
    __syncthreads();
    if (threadIdx.x == 0) {
        int tot = 0;
#pragma unroll
        for (int i = 0; i < 8; i++) tot += wsum[i];
        g_rowsum[m] = tot;
    }
}

// ---------------------------------------------------------------------------
// Kernel 2: unpack int4 nibbles -> exact f16 weights.
// ---------------------------------------------------------------------------
__global__ __launch_bounds__(256) void unpack_kernel(const int* __restrict__ qweight) {
    const int o = blockIdx.x;
    const int t = threadIdx.x;
    const int* qrow = qweight + (size_t)o * QW + 8 * t;
    int4 q0 = *reinterpret_cast<const int4*>(qrow);
    int4 q1 = *reinterpret_cast<const int4*>(qrow + 4);
    const int* ql = &q0.x;
    const int* qh = &q1.x;

    __half2 h[8];
#pragma unroll
    for (int c = 0; c < 4; c++) {
        h[c]     = __halves2half2(__int2half_rn((ql[c] >> 4) & 15), __int2half_rn(ql[c] & 15));
        h[4 + c] = __halves2half2(__int2half_rn((qh[c] >> 4) & 15), __int2half_rn(qh[c] & 15));
    }
    __half* dst = g_wh + (size_t)o * K_DIM + 16 * t;
    *reinterpret_cast<int4*>(dst)     = *reinterpret_cast<int4*>(&h[0]);
    *reinterpret_cast<int4*>(dst + 8) = *reinterpret_cast<int4*>(&h[4]);
}

// ---------------------------------------------------------------------------
// Kernel 3: pure-HMMA f16 GEMM, exact integer math.
// Block tile 128x128, BK=64, 8 warps (4Mx2N), warp tile 32x64.
// Double-buffered cp.async, XOR-swizzled 128B smem rows.
// __launch_bounds__(256,2): 2 CTAs/SM (4 warps/SMSP) to cover ldsm->HMMA
// latency chains; 2 x 64KB dynamic smem fits 228KB/SM.
// ---------------------------------------------------------------------------
#define BK 64
#define ROWB 128                    // bytes per smem row (= BK*2)
#define A_STG (128 * ROWB)          // 16 KB
#define STG (2 * A_STG)             // 32 KB per stage (A + B)
#define NCHUNK (K_DIM / BK)         // 64

__global__ __launch_bounds__(256, 2) void gemm_kernel(const int* __restrict__ qzeros,
                                                      const float* __restrict__ scales,
                                                      const float* __restrict__ bias,
                                                      const float* __restrict__ clampv,
                                                      float* __restrict__ out) {
    extern __shared__ __align__(128) char smem[];
    const uint32_t sb = (uint32_t)__cvta_generic_to_shared(smem);

    const int tid = threadIdx.x;
    const int wid = tid >> 5, lane = tid & 31;
    const int wm = wid & 3, wn = wid >> 2;           // 4 warps in M, 2 in N
    const int m0 = blockIdx.y * 128, n0 = blockIdx.x * 128;

    // ldmatrix per-lane addressing
    const int rin = lane & 15, seg = lane >> 4;
    int arow[2], akey[2];
#pragma unroll
    for (int mt = 0; mt < 2; mt++) {
        const int r = wm * 32 + mt * 16 + rin;
        arow[mt] = r * ROWB;
        akey[mt] = r & 7;
    }
    int brow[4], bkey[4];
#pragma unroll
    for (int oc = 0; oc < 4; oc++) {
        const int r = wn * 64 + oc * 16 + rin;
        brow[oc] = r * ROWB;
        bkey[oc] = r & 7;
    }

    // cp.async per-thread mapping: 128 rows x 8 chunks of 16B per matrix
    const int ldc = tid & 7;     // 16B chunk
    const int ldr = tid >> 3;    // row 0..31 (+32*i)

    float acc[2][8][4];
#pragma unroll
    for (int mt = 0; mt < 2; mt++)
#pragma unroll
        for (int o = 0; o < 8; o++)
#pragma unroll
            for (int r = 0; r < 4; r++) acc[mt][o][r] = 0.0f;

    auto load_chunk = [&](int kt, int stage) {
        const uint32_t ab = sb + stage * STG;
        const uint32_t bb = ab + A_STG;
        const size_t koff = (size_t)kt * BK + ldc * 8;   // halves
#pragma unroll
        for (int i = 0; i < 4; i++) {
            const int r = ldr + 32 * i;
            const uint32_t sw = (uint32_t)(r * ROWB + ((ldc ^ (r & 7)) << 4));
            cp16(ab + sw, g_xh + (size_t)(m0 + r) * K_DIM + koff);
            cp16(bb + sw, g_wh + (size_t)(n0 + r) * K_DIM + koff);
        }
        CP_COMMIT();
    };

    load_chunk(0, 0);

#pragma unroll 1
    for (int kt = 0; kt < NCHUNK; kt++) {
        if (kt + 1 < NCHUNK) {
            load_chunk(kt + 1, (kt + 1) & 1);
            asm volatile("cp.async.wait_group 1;");
        } else {
            asm volatile("cp.async.wait_group 0;");
        }
        __syncthreads();

        const uint32_t ab = sb + (kt & 1) * STG;
        const uint32_t bb = ab + A_STG;
#pragma unroll
        for (int s = 0; s < 4; s++) {               // four k16 steps
            const int cidx = 2 * s + seg;
            int a[2][4], b[4][4];
#pragma unroll
            for (int mt = 0; mt < 2; mt++)
                ldsm4(a[mt][0], a[mt][1], a[mt][2], a[mt][3],
                      ab + (uint32_t)(arow[mt] + ((cidx ^ akey[mt]) << 4)));
#pragma unroll
            for (int oc = 0; oc < 4; oc++)
                ldsm4(b[oc][0], b[oc][1], b[oc][2], b[oc][3],
                      bb + (uint32_t)(brow[oc] + ((cidx ^ bkey[oc]) << 4)));
#pragma unroll
            for (int mt = 0; mt < 2; mt++)
#pragma unroll
                for (int oc = 0; oc < 4; oc++) {
                    mma_f16(acc[mt][oc * 2 + 0], a[mt], b[oc][0], b[oc][2]);
                    mma_f16(acc[mt][oc * 2 + 1], a[mt], b[oc][1], b[oc][3]);
                }
        }
        __syncthreads();
    }

    // ---- epilogue: out = sc*(acc - z*rowsum) + bias (all exact integers)
    const float cv = clampv[0];
    const float a_scale = cv / 127.0f;
    const int g = lane >> 2, tg = lane & 3;

    float scf[8][2], bif[8][2], zzf[8][2];
#pragma unroll
    for (int o = 0; o < 8; o++) {
        const int col = n0 + wn * 64 + (o >> 1) * 16 + (o & 1) * 8 + tg * 2;
#pragma unroll
        for (int j = 0; j < 2; j++) {
            scf[o][j] = scales[col + j] * a_scale;
            zzf[o][j] = (float)qzeros[col + j];
            bif[o][j] = bias[col + j];
        }
    }

#pragma unroll
    for (int mt = 0; mt < 2; mt++)
#pragma unroll
        for (int h = 0; h < 2; h++) {
            const int row = m0 + wm * 32 + mt * 16 + h * 8 + g;
            const float rs = (float)g_rowsum[row];
            float* orow = out + (size_t)row * N_DIM + n0 + wn * 64;
#pragma unroll
            for (int o = 0; o < 8; o++) {
                float2 v;
                v.x = scf[o][0] * (acc[mt][o][h * 2 + 0] - zzf[o][0] * rs) + bif[o][0];
                v.y = scf[o][1] * (acc[mt][o][h * 2 + 1] - zzf[o][1] * rs) + bif[o][1];
                *reinterpret_cast<float2*>(orow + (o >> 1) * 16 + (o & 1) * 8 + tg * 2) = v;
            }
        }
}

// ---------------------------------------------------------------------------
extern "C" void kernel_launch(void* const* d_in, const int* in_sizes, int n_in,
                              void* d_out, int out_size) {
    const float* x       = (const float*)d_in[0];   // [4096, 4096] f32
    const int*   qweight = (const int*)  d_in[1];   // [11008, 2048] i32
    const int*   qzeros  = (const int*)  d_in[2];   // [11008, 1] i32
    const float* scales  = (const float*)d_in[3];   // [11008, 1] f32
    const float* bias    = (const float*)d_in[4];   // [11008] f32
    const float* clampv  = (const float*)d_in[5];   // [1] f32
    float* out = (float*)d_out;                     // [4096, 11008] f32

    cudaFuncSetAttribute(gemm_kernel, cudaFuncAttributeMaxDynamicSharedMemorySize, 2 * STG);

    quantize_kernel<<<M_DIM, 256>>>(x, clampv);
    unpack_kernel<<<N_DIM, 256>>>(qweight);
    gemm_kernel<<<dim3(N_DIM / 128, M_DIM / 128), 256, 2 * STG>>>(qzeros, scales, bias,
                                                                  clampv, out);
}